// round 3
// baseline (speedup 1.0000x reference)
#include <cuda_runtime.h>
#include <math.h>

#define Nn   8000
#define NPc  1000
#define Bc   8
#define Fc   1000
#define HCc  32
#define Ecap 80000
#define TRIc 499500
#define HIDc 128
#define EPSc 1e-5f
#define HVSTRIDE (Nn * HCc)

#define NB   148
#define CB   40
#define NG   (NB - CB)
#define NTH  1024
#define CWARPS (CB * 32)

#define CHUNK  1024
#define NCHUNK ((TRIc + CHUNK - 1) / CHUNK)   // 488
#define GCH    4
#define SPLIT  (NG * GCH)                      // 432

// ---------------- persistent scratch ----------------
__device__ int    g_bar[32];                   // monotonic barrier counters (never reset)
__device__ float  g_deg[Nn];
__device__ int    g_cnt[Nn];
__device__ int    g_rowptr[Nn + 1];
__device__ int    g_cursor[Nn];
__device__ float2 g_cedge[Ecap];               // (.x = local src idx bitcast, .y = weight)
__device__ float  g_bufA[Nn * HCc];
__device__ float  g_bufB[Nn * HCc];
__device__ float  g_bufC[Nn * HCc];
__device__ float  g_hv[5 * HVSTRIDE];
__device__ float  g_emb[Bc * 96];
__device__ float  g_y1[Bc * HIDc];

// Monotonic inter-block barrier: safe across graph replays without reset.
__device__ __forceinline__ void gbar(int slot, int nb) {
    __syncthreads();
    if (threadIdx.x == 0) {
        __threadfence();
        int r = atomicAdd(&g_bar[slot], 1);
        int target = (r / nb + 1) * nb;
        while (atomicAdd(&g_bar[slot], 0) < target) { }
    }
    __syncthreads();
}

// ---------------- Clenshaw gather pass (warp per node, contiguous ranges) ----------------
__device__ void gather_pass(const float* __restrict__ V, int vshift,
                            const float* __restrict__ P, int pshift,
                            const float* __restrict__ C, int clocal,
                            float* __restrict__ T)
{
    int w = blockIdx.x * 32 + (threadIdx.x >> 5);
    int l = threadIdx.x & 31;
    int d0 = (int)(((long long)w * Nn) / CWARPS);
    int d1 = (int)(((long long)(w + 1) * Nn) / CWARPS);
    for (int d = d0; d < d1; d++) {
        int b = d / NPc, loc = d - b * NPc;
        float v = __ldcg(V + (size_t)(vshift ? loc : d) * HCc + l);
        if (P) v -= __ldcg(P + (size_t)(pshift ? loc : d) * HCc + l);
        const float* Cb = clocal ? C : (C + (size_t)b * NPc * HCc);
        int i0 = __ldcg(g_rowptr + d), i1 = __ldcg(g_rowptr + d + 1);
        float s = 0.f;
        for (int base = i0; base < i1; base += 32) {
            int e = base + l;
            int idx = 0; float we = 0.f;
            if (e < i1) { float2 ed = __ldcg(&g_cedge[e]); idx = __float_as_int(ed.x); we = ed.y; }
            int n = min(32, i1 - base);
#pragma unroll 4
            for (int q = 0; q < n; q++) {
                int   si = __shfl_sync(0xFFFFFFFFu, idx, q);
                float wq = __shfl_sync(0xFFFFFFFFu, we, q);
                s = fmaf(wq, __ldcg(Cb + (size_t)si * HCc + l), s);
            }
        }
        T[(size_t)d * HCc + l] = fmaf(2.f, s, v);
    }
}

// ---------------- final Clenshaw pass: tanh + pool + next-layer v-tables ----------------
__device__ void final_pass(const float* __restrict__ V, int vshift,
                           const float* __restrict__ Pm,
                           const float* __restrict__ C1,
                           const float* __restrict__ bias,
                           const float* sW,            // smem [5][32][32] or null
                           float* __restrict__ hv, int Lcol)
{
    int w = blockIdx.x * 32 + (threadIdx.x >> 5);
    int l = threadIdx.x & 31;
    int d0 = (int)(((long long)w * Nn) / CWARPS);
    int d1 = (int)(((long long)(w + 1) * Nn) / CWARPS);
    float bl = __ldg(bias + l);
    float poolacc = 0.f; int curb = -1;
    for (int d = d0; d < d1; d++) {
        int b = d / NPc, loc = d - b * NPc;
        float v = __ldcg(V + (size_t)(vshift ? loc : d) * HCc + l)
                - __ldcg(Pm + (size_t)d * HCc + l) + bl;
        const float* Cb = C1 + (size_t)b * NPc * HCc;
        int i0 = __ldcg(g_rowptr + d), i1 = __ldcg(g_rowptr + d + 1);
        float s = 0.f;
        for (int base = i0; base < i1; base += 32) {
            int e = base + l;
            int idx = 0; float we = 0.f;
            if (e < i1) { float2 ed = __ldcg(&g_cedge[e]); idx = __float_as_int(ed.x); we = ed.y; }
            int n = min(32, i1 - base);
#pragma unroll 4
            for (int q = 0; q < n; q++) {
                int   si = __shfl_sync(0xFFFFFFFFu, idx, q);
                float wq = __shfl_sync(0xFFFFFFFFu, we, q);
                s = fmaf(wq, __ldcg(Cb + (size_t)si * HCc + l), s);
            }
        }
        float h = tanhf(v + s);
        if (b != curb) {
            if (curb >= 0) atomicAdd(&g_emb[curb * 96 + Lcol + l], poolacc);
            poolacc = 0.f; curb = b;
        }
        poolacc += h;
        if (sW) {
            float a0 = 0.f, a1 = 0.f, a2 = 0.f, a3 = 0.f, a4 = 0.f;
#pragma unroll
            for (int j = 0; j < HCc; j++) {
                float hj = __shfl_sync(0xFFFFFFFFu, h, j);
                a0 = fmaf(hj, sW[0 * 1024 + j * 32 + l], a0);
                a1 = fmaf(hj, sW[1 * 1024 + j * 32 + l], a1);
                a2 = fmaf(hj, sW[2 * 1024 + j * 32 + l], a2);
                a3 = fmaf(hj, sW[3 * 1024 + j * 32 + l], a3);
                a4 = fmaf(hj, sW[4 * 1024 + j * 32 + l], a4);
            }
            hv[0 * HVSTRIDE + (size_t)d * HCc + l] = a0;
            hv[1 * HVSTRIDE + (size_t)d * HCc + l] = a1;
            hv[2 * HVSTRIDE + (size_t)d * HCc + l] = a2;
            hv[3 * HVSTRIDE + (size_t)d * HCc + l] = a3;
            hv[4 * HVSTRIDE + (size_t)d * HCc + l] = a4;
        }
    }
    if (curb >= 0) atomicAdd(&g_emb[curb * 96 + Lcol + l], poolacc);
}

// ---------------- fused fbn + W1-stream GEMM with tree-reduce epilogue ----------------
__device__ void gemm_chunks(int c0, int cend, int cstep,
                            const float* __restrict__ x,
                            const float* __restrict__ W1,
                            const float* __restrict__ bng,
                            const float* __restrict__ bnb,
                            float* buf)
{
    int t = threadIdx.x, wp = t >> 5, l = t & 31;
    float acc[Bc][4];
#pragma unroll
    for (int b = 0; b < Bc; b++)
#pragma unroll
        for (int q = 0; q < 4; q++) acc[b][q] = 0.f;

    for (int c = c0; c < cend; c += cstep) {
        int fbase = c * CHUNK;
        __syncthreads();
        // phase A: compute fbn for this chunk into smem [f_local][8]
        {
            int f = fbase + t;
            float res[Bc];
            if (f < TRIc) {
                float disc = 3996001.0f - 8.0f * (float)f;
                float sq = sqrtf(fmaxf(disc, 0.f));
                int i = (int)((1999.0f - sq) * 0.5f);
                i = max(0, min(i, Fc - 2));
                while (i + 1 <= Fc - 2 && (((long long)(i + 1) * (1999 - (i + 1))) >> 1) <= (long long)f) i++;
                while (i > 0 && (((long long)i * (1999 - i)) >> 1) > (long long)f) i--;
                int Si = (int)(((long long)i * (1999 - i)) >> 1);
                int j = i + 1 + (f - Si);
                float v[Bc]; float m = 0.f;
#pragma unroll
                for (int b = 0; b < Bc; b++) {
                    v[b] = __ldg(x + ((size_t)(b * Fc + i) * Fc + j));
                    m += v[b];
                }
                m *= 0.125f;
                float var = 0.f;
#pragma unroll
                for (int b = 0; b < Bc; b++) { float dd = v[b] - m; var = fmaf(dd, dd, var); }
                var *= 0.125f;
                float sc = rsqrtf(var + EPSc) * __ldg(bng + f);
                float sh = __ldg(bnb + f);
#pragma unroll
                for (int b = 0; b < Bc; b++) res[b] = (v[b] - m) * sc + sh;
            } else {
#pragma unroll
                for (int b = 0; b < Bc; b++) res[b] = 0.f;
            }
            *(float4*)&buf[t * 8]     = make_float4(res[0], res[1], res[2], res[3]);
            *(float4*)&buf[t * 8 + 4] = make_float4(res[4], res[5], res[6], res[7]);
        }
        __syncthreads();
        // phase B: stream W1 rows
        int rows = min(CHUNK, TRIc - fbase);
#pragma unroll 4
        for (int r = 0; r < 32; r++) {
            int fl = wp * 32 + r;
            if (fl >= rows) break;
            int f = fbase + fl;
            float4 w4  = __ldcs((const float4*)(W1 + (size_t)f * HIDc + l * 4));
            float4 fb0 = *(const float4*)&buf[fl * 8];
            float4 fb1 = *(const float4*)&buf[fl * 8 + 4];
            acc[0][0] = fmaf(fb0.x, w4.x, acc[0][0]); acc[0][1] = fmaf(fb0.x, w4.y, acc[0][1]);
            acc[0][2] = fmaf(fb0.x, w4.z, acc[0][2]); acc[0][3] = fmaf(fb0.x, w4.w, acc[0][3]);
            acc[1][0] = fmaf(fb0.y, w4.x, acc[1][0]); acc[1][1] = fmaf(fb0.y, w4.y, acc[1][1]);
            acc[1][2] = fmaf(fb0.y, w4.z, acc[1][2]); acc[1][3] = fmaf(fb0.y, w4.w, acc[1][3]);
            acc[2][0] = fmaf(fb0.z, w4.x, acc[2][0]); acc[2][1] = fmaf(fb0.z, w4.y, acc[2][1]);
            acc[2][2] = fmaf(fb0.z, w4.z, acc[2][2]); acc[2][3] = fmaf(fb0.z, w4.w, acc[2][3]);
            acc[3][0] = fmaf(fb0.w, w4.x, acc[3][0]); acc[3][1] = fmaf(fb0.w, w4.y, acc[3][1]);
            acc[3][2] = fmaf(fb0.w, w4.z, acc[3][2]); acc[3][3] = fmaf(fb0.w, w4.w, acc[3][3]);
            acc[4][0] = fmaf(fb1.x, w4.x, acc[4][0]); acc[4][1] = fmaf(fb1.x, w4.y, acc[4][1]);
            acc[4][2] = fmaf(fb1.x, w4.z, acc[4][2]); acc[4][3] = fmaf(fb1.x, w4.w, acc[4][3]);
            acc[5][0] = fmaf(fb1.y, w4.x, acc[5][0]); acc[5][1] = fmaf(fb1.y, w4.y, acc[5][1]);
            acc[5][2] = fmaf(fb1.y, w4.z, acc[5][2]); acc[5][3] = fmaf(fb1.y, w4.w, acc[5][3]);
            acc[6][0] = fmaf(fb1.z, w4.x, acc[6][0]); acc[6][1] = fmaf(fb1.z, w4.y, acc[6][1]);
            acc[6][2] = fmaf(fb1.z, w4.z, acc[6][2]); acc[6][3] = fmaf(fb1.z, w4.w, acc[6][3]);
            acc[7][0] = fmaf(fb1.w, w4.x, acc[7][0]); acc[7][1] = fmaf(fb1.w, w4.y, acc[7][1]);
            acc[7][2] = fmaf(fb1.w, w4.z, acc[7][2]); acc[7][3] = fmaf(fb1.w, w4.w, acc[7][3]);
        }
    }
    __syncthreads();
    // tree reduce across 32 warps using 16 x 1024-float smem regions
    for (int half = 16; half >= 1; half >>= 1) {
        if (wp >= half && wp < 2 * half) {
            float* reg = buf + (wp - half) * 1024;
#pragma unroll
            for (int b = 0; b < Bc; b++)
                *(float4*)&reg[b * HIDc + l * 4] =
                    make_float4(acc[b][0], acc[b][1], acc[b][2], acc[b][3]);
        }
        __syncthreads();
        if (wp < half) {
            float* reg = buf + wp * 1024;
#pragma unroll
            for (int b = 0; b < Bc; b++) {
                float4 z = *(const float4*)&reg[b * HIDc + l * 4];
                acc[b][0] += z.x; acc[b][1] += z.y; acc[b][2] += z.z; acc[b][3] += z.w;
            }
        }
        __syncthreads();
    }
    if (wp == 0) {
#pragma unroll
        for (int b = 0; b < Bc; b++)
#pragma unroll
            for (int q = 0; q < 4; q++)
                atomicAdd(&g_y1[b * HIDc + l * 4 + q], acc[b][q]);
    }
}

// ---------------- the mega kernel ----------------
__global__ void __launch_bounds__(NTH, 1)
mega_kernel(const float* __restrict__ x,
            const int* __restrict__ src, const int* __restrict__ dst, int E,
            const float* __restrict__ cw0, const float* __restrict__ cb0,
            const float* __restrict__ cw1, const float* __restrict__ cb1,
            const float* __restrict__ cw2, const float* __restrict__ cb2,
            const float* __restrict__ bnhg, const float* __restrict__ bnhb,
            const float* __restrict__ bng, const float* __restrict__ bnb,
            const float* __restrict__ W1, const float* __restrict__ b1,
            const float* __restrict__ g1, const float* __restrict__ be1,
            const float* __restrict__ W2, const float* __restrict__ b2,
            const float* __restrict__ g2, const float* __restrict__ be2,
            const float* __restrict__ W3, const float* __restrict__ b3,
            const float* __restrict__ g3, const float* __restrict__ be3,
            const float* __restrict__ W4, const float* __restrict__ b4,
            float* __restrict__ out)
{
    extern __shared__ float buf[];   // 64 KB dynamic
    const int blk = blockIdx.x, t = threadIdx.x;

    // zero per-launch scratch (all blocks), then global init barrier
    {
        int gi = blk * NTH + t;
        if (gi < Nn) { g_deg[gi] = 0.f; g_cnt[gi] = 0; }
        else if (gi < Nn + Bc * 96) g_emb[gi - Nn] = 0.f;
        else if (gi < Nn + Bc * 96 + Bc * HIDc) g_y1[gi - Nn - Bc * 96] = 0.f;
    }
    gbar(0, NB);

    if (blk < CB) {
        // ===== cheb role =====
        // count degrees / in-counts
        for (int e = blk * NTH + t; e < E; e += CB * NTH) {
            atomicAdd(&g_deg[__ldg(src + e)], 1.f);
            atomicAdd(&g_cnt[__ldg(dst + e)], 1);
        }
        gbar(1, CB);
        // exclusive scan (block 0 only)
        if (blk == 0) {
            int* part = (int*)buf;
            int local[8]; int sum = 0;
#pragma unroll
            for (int q = 0; q < 8; q++) {
                int idx = t * 8 + q;
                int c = (idx < Nn) ? __ldcg(g_cnt + idx) : 0;
                local[q] = sum; sum += c;
            }
            part[t] = sum;
            __syncthreads();
            for (int off = 1; off < 1024; off <<= 1) {
                int v = (t >= off) ? part[t - off] : 0;
                __syncthreads();
                part[t] += v;
                __syncthreads();
            }
            int pref = (t > 0) ? part[t - 1] : 0;
#pragma unroll
            for (int q = 0; q < 8; q++) {
                int idx = t * 8 + q;
                if (idx < Nn) { g_rowptr[idx] = pref + local[q]; g_cursor[idx] = pref + local[q]; }
            }
            if (t == 0) g_rowptr[Nn] = part[1023];
        }
        gbar(2, CB);
        // build CSR
        for (int e = blk * NTH + t; e < E; e += CB * NTH) {
            int s_ = __ldg(src + e), d_ = __ldg(dst + e);
            float ds = __ldcg(g_deg + s_), dd = __ldcg(g_deg + d_);
            float wgt = -((ds > 0.f) ? rsqrtf(ds) : 0.f) * ((dd > 0.f) ? rsqrtf(dd) : 0.f);
            int pos = atomicAdd(&g_cursor[d_], 1);
            g_cedge[pos] = make_float2(__int_as_float(s_ % NPc), wgt);
        }
        gbar(3, CB);

        const int FS = Fc * HCc;
        int slot = 4;
        // ---- layer 0 (identity input: v-tables are cw0 planes, local-indexed) ----
        gather_pass(cw0 + 3 * FS, 1, nullptr, 0, cw0 + 4 * FS, 1, g_bufA); gbar(slot++, CB);
        gather_pass(cw0 + 2 * FS, 1, cw0 + 4 * FS, 1, g_bufA, 0, g_bufB); gbar(slot++, CB);
        gather_pass(cw0 + 1 * FS, 1, g_bufA, 0, g_bufB, 0, g_bufC);       gbar(slot++, CB);
        for (int idx = t; idx < 5 * 1024; idx += NTH) buf[idx] = __ldg(cw1 + idx);
        __syncthreads();
        final_pass(cw0, 1, g_bufB, g_bufC, cb0, buf, g_hv, 0);            gbar(slot++, CB);
        // ---- layer 1 ----
        gather_pass(g_hv + 3 * HVSTRIDE, 0, nullptr, 0, g_hv + 4 * HVSTRIDE, 0, g_bufA); gbar(slot++, CB);
        gather_pass(g_hv + 2 * HVSTRIDE, 0, g_hv + 4 * HVSTRIDE, 0, g_bufA, 0, g_bufB);  gbar(slot++, CB);
        gather_pass(g_hv + 1 * HVSTRIDE, 0, g_bufA, 0, g_bufB, 0, g_bufC);               gbar(slot++, CB);
        for (int idx = t; idx < 5 * 1024; idx += NTH) buf[idx] = __ldg(cw2 + idx);
        __syncthreads();
        final_pass(g_hv, 0, g_bufB, g_bufC, cb1, buf, g_hv, 32);                          gbar(slot++, CB);
        // ---- layer 2 ----
        gather_pass(g_hv + 3 * HVSTRIDE, 0, nullptr, 0, g_hv + 4 * HVSTRIDE, 0, g_bufA); gbar(slot++, CB);
        gather_pass(g_hv + 2 * HVSTRIDE, 0, g_hv + 4 * HVSTRIDE, 0, g_bufA, 0, g_bufB);  gbar(slot++, CB);
        gather_pass(g_hv + 1 * HVSTRIDE, 0, g_bufA, 0, g_bufB, 0, g_bufC);               gbar(slot++, CB);
        final_pass(g_hv, 0, g_bufB, g_bufC, cb2, nullptr, nullptr, 64);
        // ---- tail share of the W1 stream ----
        gemm_chunks(SPLIT + blk, NCHUNK, CB, x, W1, bng, bnb, buf);
    } else {
        // ===== GEMM role =====
        int c0 = (blk - CB) * GCH;
        gemm_chunks(c0, c0 + GCH, 1, x, W1, bng, bnb, buf);
    }

    gbar(31, NB);   // everything done

    // ===== head (block 0) =====
    if (blk != 0) return;
    float* a1 = buf;          // 1024
    float* a2 = buf + 1024;   // 512
    float* a3 = buf + 1536;   // 512
    float* lg = buf + 2048;   // 16

    // hbn -> out[16:784]
    if (t < 96) {
        float e[Bc]; float m = 0.f;
#pragma unroll
        for (int b = 0; b < Bc; b++) { e[b] = __ldcg(&g_emb[b * 96 + t]) * (1.f / (float)NPc); m += e[b]; }
        m *= 0.125f;
        float v = 0.f;
#pragma unroll
        for (int b = 0; b < Bc; b++) { float dd = e[b] - m; v = fmaf(dd, dd, v); }
        v *= 0.125f;
        float sc = rsqrtf(v + EPSc) * __ldg(bnhg + t);
        float sh = __ldg(bnhb + t);
#pragma unroll
        for (int b = 0; b < Bc; b++) out[16 + b * 96 + t] = (e[b] - m) * sc + sh;
    }

    if (t < 1024) a1[t] = __ldcg(&g_y1[t]) + __ldg(&b1[t & 127]);
    __syncthreads();
    if (t < 128) {
        float m = 0.f;
#pragma unroll
        for (int b = 0; b < Bc; b++) m += a1[b * 128 + t];
        m *= 0.125f;
        float v = 0.f;
#pragma unroll
        for (int b = 0; b < Bc; b++) { float dd = a1[b * 128 + t] - m; v = fmaf(dd, dd, v); }
        v *= 0.125f;
        float sc = rsqrtf(v + EPSc) * __ldg(g1 + t);
        float sh = __ldg(be1 + t);
#pragma unroll
        for (int b = 0; b < Bc; b++) {
            float z = (a1[b * 128 + t] - m) * sc + sh;
            a1[b * 128 + t] = z > 0.f ? z : 0.f;
        }
    }
    __syncthreads();
    if (t < 512) {
        int b = t >> 6, h = t & 63;
        float s = __ldg(b2 + h);
        for (int j = 0; j < 128; j++) s = fmaf(a1[b * 128 + j], __ldg(W2 + j * 64 + h), s);
        a2[t] = s;
    }
    __syncthreads();
    if (t < 64) {
        float m = 0.f;
#pragma unroll
        for (int b = 0; b < Bc; b++) m += a2[b * 64 + t];
        m *= 0.125f;
        float v = 0.f;
#pragma unroll
        for (int b = 0; b < Bc; b++) { float dd = a2[b * 64 + t] - m; v = fmaf(dd, dd, v); }
        v *= 0.125f;
        float sc = rsqrtf(v + EPSc) * __ldg(g2 + t);
        float sh = __ldg(be2 + t);
#pragma unroll
        for (int b = 0; b < Bc; b++) {
            float z = (a2[b * 64 + t] - m) * sc + sh;
            a2[b * 64 + t] = z > 0.f ? z : 0.f;
        }
    }
    __syncthreads();
    if (t < 512) {
        int b = t >> 6, h = t & 63;
        float s = __ldg(b3 + h);
        for (int j = 0; j < 64; j++) s = fmaf(a2[b * 64 + j], __ldg(W3 + j * 64 + h), s);
        a3[t] = s;
    }
    __syncthreads();
    if (t < 64) {
        float m = 0.f;
#pragma unroll
        for (int b = 0; b < Bc; b++) m += a3[b * 64 + t];
        m *= 0.125f;
        float v = 0.f;
#pragma unroll
        for (int b = 0; b < Bc; b++) { float dd = a3[b * 64 + t] - m; v = fmaf(dd, dd, v); }
        v *= 0.125f;
        float sc = rsqrtf(v + EPSc) * __ldg(g3 + t);
        float sh = __ldg(be3 + t);
#pragma unroll
        for (int b = 0; b < Bc; b++) {
            float z = (a3[b * 64 + t] - m) * sc + sh;
            a3[b * 64 + t] = z > 0.f ? z : 0.f;
        }
    }
    __syncthreads();
    if (t < 16) {
        int b = t >> 1, c = t & 1;
        float s = __ldg(b4 + c);
        for (int j = 0; j < 64; j++) s = fmaf(a3[b * 64 + j], __ldg(W4 + j * 2 + c), s);
        lg[t] = s;
    }
    __syncthreads();
    if (t < 8) {
        float l0 = lg[t * 2], l1 = lg[t * 2 + 1];
        float m = fmaxf(l0, l1);
        float lse = m + logf(expf(l0 - m) + expf(l1 - m));
        out[t * 2 + 0] = l0 - lse;
        out[t * 2 + 1] = l1 - lse;
    }
}

// ---------------- host driver ----------------
extern "C" void kernel_launch(void* const* d_in, const int* in_sizes, int n_in,
                              void* d_out, int out_size) {
    const float* x    = (const float*)d_in[0];
    const int*   ei   = (const int*)d_in[1];
    int E = in_sizes[1] / 2;
    const int* src = ei;
    const int* dst = ei + E;
    const float* cw0  = (const float*)d_in[3];
    const float* cb0  = (const float*)d_in[4];
    const float* cw1  = (const float*)d_in[5];
    const float* cb1  = (const float*)d_in[6];
    const float* cw2  = (const float*)d_in[7];
    const float* cb2  = (const float*)d_in[8];
    const float* bnhg = (const float*)d_in[9];
    const float* bnhb = (const float*)d_in[10];
    const float* bng  = (const float*)d_in[11];
    const float* bnb  = (const float*)d_in[12];
    const float* w1   = (const float*)d_in[13];
    const float* b1   = (const float*)d_in[14];
    const float* g1   = (const float*)d_in[15];
    const float* be1  = (const float*)d_in[16];
    const float* W2   = (const float*)d_in[17];
    const float* b2   = (const float*)d_in[18];
    const float* g2   = (const float*)d_in[19];
    const float* be2  = (const float*)d_in[20];
    const float* W3   = (const float*)d_in[21];
    const float* b3   = (const float*)d_in[22];
    const float* g3   = (const float*)d_in[23];
    const float* be3  = (const float*)d_in[24];
    const float* W4   = (const float*)d_in[25];
    const float* b4   = (const float*)d_in[26];
    float* out = (float*)d_out;

    cudaFuncSetAttribute(mega_kernel, cudaFuncAttributeMaxDynamicSharedMemorySize, 65536);
    mega_kernel<<<NB, NTH, 65536>>>(x, src, dst, E,
                                    cw0, cb0, cw1, cb1, cw2, cb2,
                                    bnhg, bnhb, bng, bnb,
                                    w1, b1, g1, be1, W2, b2, g2, be2,
                                    W3, b3, g3, be3, W4, b4, out);
}

// round 4
// speedup vs baseline: 1.0084x; 1.0084x over previous
#include <cuda_runtime.h>
#include <math.h>

#define Nn   8000
#define NPc  1000
#define Bc   8
#define Fc   1000
#define HCc  32
#define Ecap 80000
#define TRIc 499500
#define HIDc 128
#define EPSc 1e-5f
#define HVSTRIDE (Nn * HCc)

#define NB   148
#define CB   56
#define NG   (NB - CB)            // 92
#define NTH  512
#define WARPS (NTH / 32)          // 16
#define CWARPS (CB * WARPS)       // 896

#define CHUNK  1024
#define NCHUNK ((TRIc + CHUNK - 1) / CHUNK)   // 488
#define GCH    5
#define SPLIT  (NG * GCH)                      // 460

// ---------------- persistent scratch ----------------
__device__ int    g_bar[32];                   // monotonic barrier counters
__device__ float  g_deg[Nn];
__device__ int    g_cnt[Nn];
__device__ int    g_rowptr[Nn + 1];
__device__ int    g_cursor[Nn];
__device__ float2 g_cedge[Ecap];
__device__ float  g_bufA[Nn * HCc];
__device__ float  g_bufB[Nn * HCc];
__device__ float  g_bufC[Nn * HCc];
__device__ float  g_hv[5 * HVSTRIDE];
__device__ float  g_emb[Bc * 96];
__device__ float  g_y1[Bc * HIDc];

__device__ __forceinline__ void gbar(int slot, int nb) {
    __syncthreads();
    if (threadIdx.x == 0) {
        __threadfence();
        int r = atomicAdd(&g_bar[slot], 1);
        int target = (r / nb + 1) * nb;
        while (atomicAdd(&g_bar[slot], 0) < target) { }
    }
    __syncthreads();
}

// ---------------- Clenshaw gather pass ----------------
__device__ void gather_pass(const float* __restrict__ V, int vshift,
                            const float* __restrict__ P, int pshift,
                            const float* __restrict__ C, int clocal,
                            float* __restrict__ T)
{
    int w = blockIdx.x * WARPS + (threadIdx.x >> 5);
    int l = threadIdx.x & 31;
    int d0 = (int)(((long long)w * Nn) / CWARPS);
    int d1 = (int)(((long long)(w + 1) * Nn) / CWARPS);
    for (int d = d0; d < d1; d++) {
        int b = d / NPc, loc = d - b * NPc;
        float v = __ldcg(V + (size_t)(vshift ? loc : d) * HCc + l);
        if (P) v -= __ldcg(P + (size_t)(pshift ? loc : d) * HCc + l);
        const float* Cb = clocal ? C : (C + (size_t)b * NPc * HCc);
        int i0 = __ldcg(g_rowptr + d), i1 = __ldcg(g_rowptr + d + 1);
        float s = 0.f;
        for (int base = i0; base < i1; base += 32) {
            int e = base + l;
            int idx = 0; float we = 0.f;
            if (e < i1) { float2 ed = __ldcg(&g_cedge[e]); idx = __float_as_int(ed.x); we = ed.y; }
            int n = min(32, i1 - base);
#pragma unroll 4
            for (int q = 0; q < n; q++) {
                int   si = __shfl_sync(0xFFFFFFFFu, idx, q);
                float wq = __shfl_sync(0xFFFFFFFFu, we, q);
                s = fmaf(wq, __ldcg(Cb + (size_t)si * HCc + l), s);
            }
        }
        T[(size_t)d * HCc + l] = fmaf(2.f, s, v);
    }
}

// ---------------- final Clenshaw pass: tanh + pool + next-layer v-tables ----------------
__device__ void final_pass(const float* __restrict__ V, int vshift,
                           const float* __restrict__ Pm,
                           const float* __restrict__ C1,
                           const float* __restrict__ bias,
                           const float* sW, float* __restrict__ hv, int Lcol)
{
    int w = blockIdx.x * WARPS + (threadIdx.x >> 5);
    int l = threadIdx.x & 31;
    int d0 = (int)(((long long)w * Nn) / CWARPS);
    int d1 = (int)(((long long)(w + 1) * Nn) / CWARPS);
    float bl = __ldg(bias + l);
    float poolacc = 0.f; int curb = -1;
    for (int d = d0; d < d1; d++) {
        int b = d / NPc, loc = d - b * NPc;
        float v = __ldcg(V + (size_t)(vshift ? loc : d) * HCc + l)
                - __ldcg(Pm + (size_t)d * HCc + l) + bl;
        const float* Cb = C1 + (size_t)b * NPc * HCc;
        int i0 = __ldcg(g_rowptr + d), i1 = __ldcg(g_rowptr + d + 1);
        float s = 0.f;
        for (int base = i0; base < i1; base += 32) {
            int e = base + l;
            int idx = 0; float we = 0.f;
            if (e < i1) { float2 ed = __ldcg(&g_cedge[e]); idx = __float_as_int(ed.x); we = ed.y; }
            int n = min(32, i1 - base);
#pragma unroll 4
            for (int q = 0; q < n; q++) {
                int   si = __shfl_sync(0xFFFFFFFFu, idx, q);
                float wq = __shfl_sync(0xFFFFFFFFu, we, q);
                s = fmaf(wq, __ldcg(Cb + (size_t)si * HCc + l), s);
            }
        }
        float h = tanhf(v + s);
        if (b != curb) {
            if (curb >= 0) atomicAdd(&g_emb[curb * 96 + Lcol + l], poolacc);
            poolacc = 0.f; curb = b;
        }
        poolacc += h;
        if (sW) {
            float a0 = 0.f, a1 = 0.f, a2 = 0.f, a3 = 0.f, a4 = 0.f;
#pragma unroll
            for (int j = 0; j < HCc; j++) {
                float hj = __shfl_sync(0xFFFFFFFFu, h, j);
                a0 = fmaf(hj, sW[0 * 1024 + j * 32 + l], a0);
                a1 = fmaf(hj, sW[1 * 1024 + j * 32 + l], a1);
                a2 = fmaf(hj, sW[2 * 1024 + j * 32 + l], a2);
                a3 = fmaf(hj, sW[3 * 1024 + j * 32 + l], a3);
                a4 = fmaf(hj, sW[4 * 1024 + j * 32 + l], a4);
            }
            hv[0 * HVSTRIDE + (size_t)d * HCc + l] = a0;
            hv[1 * HVSTRIDE + (size_t)d * HCc + l] = a1;
            hv[2 * HVSTRIDE + (size_t)d * HCc + l] = a2;
            hv[3 * HVSTRIDE + (size_t)d * HCc + l] = a3;
            hv[4 * HVSTRIDE + (size_t)d * HCc + l] = a4;
        }
    }
    if (curb >= 0) atomicAdd(&g_emb[curb * 96 + Lcol + l], poolacc);
}

// ---------------- fused fbn + W1-stream GEMM (software-pipelined) ----------------
__device__ void gemm_chunks(int c0, int cend, int cstep,
                            const float* __restrict__ x,
                            const float* __restrict__ W1,
                            const float* __restrict__ bng,
                            const float* __restrict__ bnb,
                            float* buf)
{
    int t = threadIdx.x, wp = t >> 5, l = t & 31;
    float acc[Bc][4];
#pragma unroll
    for (int b = 0; b < Bc; b++)
#pragma unroll
        for (int q = 0; q < 4; q++) acc[b][q] = 0.f;

    for (int c = c0; c < cend; c += cstep) {
        int fbase = c * CHUNK;
        __syncthreads();
        // phase A: fbn for this chunk into smem [f_local][8] (zeros past TRIc)
        for (int ff = t; ff < CHUNK; ff += NTH) {
            int f = fbase + ff;
            float res[Bc];
            if (f < TRIc) {
                float disc = 3996001.0f - 8.0f * (float)f;
                float sq = sqrtf(fmaxf(disc, 0.f));
                int i = (int)((1999.0f - sq) * 0.5f);
                i = max(0, min(i, Fc - 2));
                while (i + 1 <= Fc - 2 && (((long long)(i + 1) * (1999 - (i + 1))) >> 1) <= (long long)f) i++;
                while (i > 0 && (((long long)i * (1999 - i)) >> 1) > (long long)f) i--;
                int Si = (int)(((long long)i * (1999 - i)) >> 1);
                int j = i + 1 + (f - Si);
                float v[Bc]; float m = 0.f;
#pragma unroll
                for (int b = 0; b < Bc; b++) {
                    v[b] = __ldg(x + ((size_t)(b * Fc + i) * Fc + j));
                    m += v[b];
                }
                m *= 0.125f;
                float var = 0.f;
#pragma unroll
                for (int b = 0; b < Bc; b++) { float dd = v[b] - m; var = fmaf(dd, dd, var); }
                var *= 0.125f;
                float sc = rsqrtf(var + EPSc) * __ldg(bng + f);
                float sh = __ldg(bnb + f);
#pragma unroll
                for (int b = 0; b < Bc; b++) res[b] = (v[b] - m) * sc + sh;
            } else {
#pragma unroll
                for (int b = 0; b < Bc; b++) res[b] = 0.f;
            }
            *(float4*)&buf[ff * 8]     = make_float4(res[0], res[1], res[2], res[3]);
            *(float4*)&buf[ff * 8 + 4] = make_float4(res[4], res[5], res[6], res[7]);
        }
        __syncthreads();
        // phase B: stream W1 rows, 8 loads in flight per thread
        const int RPW = CHUNK / WARPS;   // 64 rows per warp
        int r0 = wp * RPW;
        for (int rr = 0; rr < RPW; rr += 8) {
            float4 w[8];
#pragma unroll
            for (int u = 0; u < 8; u++) {
                int f = fbase + r0 + rr + u;
                f = min(f, TRIc - 1);               // clamp; fbn=0 kills OOB rows
                w[u] = __ldcs((const float4*)(W1 + (size_t)f * HIDc + l * 4));
            }
#pragma unroll
            for (int u = 0; u < 8; u++) {
                int fl = r0 + rr + u;
                float4 fb0 = *(const float4*)&buf[fl * 8];
                float4 fb1 = *(const float4*)&buf[fl * 8 + 4];
                acc[0][0] = fmaf(fb0.x, w[u].x, acc[0][0]); acc[0][1] = fmaf(fb0.x, w[u].y, acc[0][1]);
                acc[0][2] = fmaf(fb0.x, w[u].z, acc[0][2]); acc[0][3] = fmaf(fb0.x, w[u].w, acc[0][3]);
                acc[1][0] = fmaf(fb0.y, w[u].x, acc[1][0]); acc[1][1] = fmaf(fb0.y, w[u].y, acc[1][1]);
                acc[1][2] = fmaf(fb0.y, w[u].z, acc[1][2]); acc[1][3] = fmaf(fb0.y, w[u].w, acc[1][3]);
                acc[2][0] = fmaf(fb0.z, w[u].x, acc[2][0]); acc[2][1] = fmaf(fb0.z, w[u].y, acc[2][1]);
                acc[2][2] = fmaf(fb0.z, w[u].z, acc[2][2]); acc[2][3] = fmaf(fb0.z, w[u].w, acc[2][3]);
                acc[3][0] = fmaf(fb0.w, w[u].x, acc[3][0]); acc[3][1] = fmaf(fb0.w, w[u].y, acc[3][1]);
                acc[3][2] = fmaf(fb0.w, w[u].z, acc[3][2]); acc[3][3] = fmaf(fb0.w, w[u].w, acc[3][3]);
                acc[4][0] = fmaf(fb1.x, w[u].x, acc[4][0]); acc[4][1] = fmaf(fb1.x, w[u].y, acc[4][1]);
                acc[4][2] = fmaf(fb1.x, w[u].z, acc[4][2]); acc[4][3] = fmaf(fb1.x, w[u].w, acc[4][3]);
                acc[5][0] = fmaf(fb1.y, w[u].x, acc[5][0]); acc[5][1] = fmaf(fb1.y, w[u].y, acc[5][1]);
                acc[5][2] = fmaf(fb1.y, w[u].z, acc[5][2]); acc[5][3] = fmaf(fb1.y, w[u].w, acc[5][3]);
                acc[6][0] = fmaf(fb1.z, w[u].x, acc[6][0]); acc[6][1] = fmaf(fb1.z, w[u].y, acc[6][1]);
                acc[6][2] = fmaf(fb1.z, w[u].z, acc[6][2]); acc[6][3] = fmaf(fb1.z, w[u].w, acc[6][3]);
                acc[7][0] = fmaf(fb1.w, w[u].x, acc[7][0]); acc[7][1] = fmaf(fb1.w, w[u].y, acc[7][1]);
                acc[7][2] = fmaf(fb1.w, w[u].z, acc[7][2]); acc[7][3] = fmaf(fb1.w, w[u].w, acc[7][3]);
            }
        }
    }
    __syncthreads();
    // tree reduce across 16 warps (4 levels), regions of 1024 floats
    for (int half = 8; half >= 1; half >>= 1) {
        if (wp >= half && wp < 2 * half) {
            float* reg = buf + (wp - half) * 1024;
#pragma unroll
            for (int b = 0; b < Bc; b++)
                *(float4*)&reg[b * HIDc + l * 4] =
                    make_float4(acc[b][0], acc[b][1], acc[b][2], acc[b][3]);
        }
        __syncthreads();
        if (wp < half) {
            float* reg = buf + wp * 1024;
#pragma unroll
            for (int b = 0; b < Bc; b++) {
                float4 z = *(const float4*)&reg[b * HIDc + l * 4];
                acc[b][0] += z.x; acc[b][1] += z.y; acc[b][2] += z.z; acc[b][3] += z.w;
            }
        }
        __syncthreads();
    }
    if (wp == 0) {
#pragma unroll
        for (int b = 0; b < Bc; b++)
#pragma unroll
            for (int q = 0; q < 4; q++)
                atomicAdd(&g_y1[b * HIDc + l * 4 + q], acc[b][q]);
    }
}

// ---------------- the mega kernel ----------------
__global__ void __launch_bounds__(NTH, 1)
mega_kernel(const float* __restrict__ x,
            const int* __restrict__ src, const int* __restrict__ dst, int E,
            const float* __restrict__ cw0, const float* __restrict__ cb0,
            const float* __restrict__ cw1, const float* __restrict__ cb1,
            const float* __restrict__ cw2, const float* __restrict__ cb2,
            const float* __restrict__ bnhg, const float* __restrict__ bnhb,
            const float* __restrict__ bng, const float* __restrict__ bnb,
            const float* __restrict__ W1, const float* __restrict__ b1,
            const float* __restrict__ g1, const float* __restrict__ be1,
            const float* __restrict__ W2, const float* __restrict__ b2,
            const float* __restrict__ g2, const float* __restrict__ be2,
            const float* __restrict__ W3, const float* __restrict__ b3,
            const float* __restrict__ g3, const float* __restrict__ be3,
            const float* __restrict__ W4, const float* __restrict__ b4,
            float* __restrict__ out)
{
    extern __shared__ float buf[];   // 64 KB dynamic
    const int blk = blockIdx.x, t = threadIdx.x;

    {
        int gi = blk * NTH + t;
        if (gi < Nn) { g_deg[gi] = 0.f; g_cnt[gi] = 0; }
        else if (gi < Nn + Bc * 96) g_emb[gi - Nn] = 0.f;
        else if (gi < Nn + Bc * 96 + Bc * HIDc) g_y1[gi - Nn - Bc * 96] = 0.f;
    }
    gbar(0, NB);

    if (blk < CB) {
        // ===== cheb role =====
        for (int e = blk * NTH + t; e < E; e += CB * NTH) {
            atomicAdd(&g_deg[__ldg(src + e)], 1.f);
            atomicAdd(&g_cnt[__ldg(dst + e)], 1);
        }
        gbar(1, CB);
        if (blk == 0) {
            int* part = (int*)buf;
            int local[16]; int sum = 0;
#pragma unroll
            for (int q = 0; q < 16; q++) {
                int idx = t * 16 + q;
                int c = (idx < Nn) ? __ldcg(g_cnt + idx) : 0;
                local[q] = sum; sum += c;
            }
            part[t] = sum;
            __syncthreads();
            for (int off = 1; off < NTH; off <<= 1) {
                int v = (t >= off) ? part[t - off] : 0;
                __syncthreads();
                part[t] += v;
                __syncthreads();
            }
            int pref = (t > 0) ? part[t - 1] : 0;
#pragma unroll
            for (int q = 0; q < 16; q++) {
                int idx = t * 16 + q;
                if (idx < Nn) { g_rowptr[idx] = pref + local[q]; g_cursor[idx] = pref + local[q]; }
            }
            if (t == 0) g_rowptr[Nn] = part[NTH - 1];
        }
        gbar(2, CB);
        for (int e = blk * NTH + t; e < E; e += CB * NTH) {
            int s_ = __ldg(src + e), d_ = __ldg(dst + e);
            float ds = __ldcg(g_deg + s_), dd = __ldcg(g_deg + d_);
            float wgt = -((ds > 0.f) ? rsqrtf(ds) : 0.f) * ((dd > 0.f) ? rsqrtf(dd) : 0.f);
            int pos = atomicAdd(&g_cursor[d_], 1);
            g_cedge[pos] = make_float2(__int_as_float(s_ % NPc), wgt);
        }
        gbar(3, CB);

        const int FS = Fc * HCc;
        int slot = 4;
        // layer 0
        gather_pass(cw0 + 3 * FS, 1, nullptr, 0, cw0 + 4 * FS, 1, g_bufA); gbar(slot++, CB);
        gather_pass(cw0 + 2 * FS, 1, cw0 + 4 * FS, 1, g_bufA, 0, g_bufB); gbar(slot++, CB);
        gather_pass(cw0 + 1 * FS, 1, g_bufA, 0, g_bufB, 0, g_bufC);       gbar(slot++, CB);
        for (int idx = t; idx < 5 * 1024; idx += NTH) buf[idx] = __ldg(cw1 + idx);
        __syncthreads();
        final_pass(cw0, 1, g_bufB, g_bufC, cb0, buf, g_hv, 0);            gbar(slot++, CB);
        // layer 1
        gather_pass(g_hv + 3 * HVSTRIDE, 0, nullptr, 0, g_hv + 4 * HVSTRIDE, 0, g_bufA); gbar(slot++, CB);
        gather_pass(g_hv + 2 * HVSTRIDE, 0, g_hv + 4 * HVSTRIDE, 0, g_bufA, 0, g_bufB);  gbar(slot++, CB);
        gather_pass(g_hv + 1 * HVSTRIDE, 0, g_bufA, 0, g_bufB, 0, g_bufC);               gbar(slot++, CB);
        for (int idx = t; idx < 5 * 1024; idx += NTH) buf[idx] = __ldg(cw2 + idx);
        __syncthreads();
        final_pass(g_hv, 0, g_bufB, g_bufC, cb1, buf, g_hv, 32);                          gbar(slot++, CB);
        // layer 2
        gather_pass(g_hv + 3 * HVSTRIDE, 0, nullptr, 0, g_hv + 4 * HVSTRIDE, 0, g_bufA); gbar(slot++, CB);
        gather_pass(g_hv + 2 * HVSTRIDE, 0, g_hv + 4 * HVSTRIDE, 0, g_bufA, 0, g_bufB);  gbar(slot++, CB);
        gather_pass(g_hv + 1 * HVSTRIDE, 0, g_bufA, 0, g_bufB, 0, g_bufC);               gbar(slot++, CB);
        final_pass(g_hv, 0, g_bufB, g_bufC, cb2, nullptr, nullptr, 64);
        // tail share of the W1 stream
        gemm_chunks(SPLIT + blk, NCHUNK, CB, x, W1, bng, bnb, buf);
    } else {
        // ===== GEMM role =====
        int c0 = (blk - CB) * GCH;
        gemm_chunks(c0, c0 + GCH, 1, x, W1, bng, bnb, buf);
    }

    gbar(31, NB);

    // ===== head (block 0) =====
    if (blk != 0) return;
    float* a1 = buf;
    float* a2 = buf + 1024;
    float* a3 = buf + 1536;
    float* lg = buf + 2048;

    if (t < 96) {
        float e[Bc]; float m = 0.f;
#pragma unroll
        for (int b = 0; b < Bc; b++) { e[b] = __ldcg(&g_emb[b * 96 + t]) * (1.f / (float)NPc); m += e[b]; }
        m *= 0.125f;
        float v = 0.f;
#pragma unroll
        for (int b = 0; b < Bc; b++) { float dd = e[b] - m; v = fmaf(dd, dd, v); }
        v *= 0.125f;
        float sc = rsqrtf(v + EPSc) * __ldg(bnhg + t);
        float sh = __ldg(bnhb + t);
#pragma unroll
        for (int b = 0; b < Bc; b++) out[16 + b * 96 + t] = (e[b] - m) * sc + sh;
    }

    for (int idx = t; idx < 1024; idx += NTH) a1[idx] = __ldcg(&g_y1[idx]) + __ldg(&b1[idx & 127]);
    __syncthreads();
    if (t < 128) {
        float m = 0.f;
#pragma unroll
        for (int b = 0; b < Bc; b++) m += a1[b * 128 + t];
        m *= 0.125f;
        float v = 0.f;
#pragma unroll
        for (int b = 0; b < Bc; b++) { float dd = a1[b * 128 + t] - m; v = fmaf(dd, dd, v); }
        v *= 0.125f;
        float sc = rsqrtf(v + EPSc) * __ldg(g1 + t);
        float sh = __ldg(be1 + t);
#pragma unroll
        for (int b = 0; b < Bc; b++) {
            float z = (a1[b * 128 + t] - m) * sc + sh;
            a1[b * 128 + t] = z > 0.f ? z : 0.f;
        }
    }
    __syncthreads();
    {
        int b = t >> 6, h = t & 63;
        float s = __ldg(b2 + h);
        for (int j = 0; j < 128; j++) s = fmaf(a1[b * 128 + j], __ldg(W2 + j * 64 + h), s);
        a2[t] = s;
    }
    __syncthreads();
    if (t < 64) {
        float m = 0.f;
#pragma unroll
        for (int b = 0; b < Bc; b++) m += a2[b * 64 + t];
        m *= 0.125f;
        float v = 0.f;
#pragma unroll
        for (int b = 0; b < Bc; b++) { float dd = a2[b * 64 + t] - m; v = fmaf(dd, dd, v); }
        v *= 0.125f;
        float sc = rsqrtf(v + EPSc) * __ldg(g2 + t);
        float sh = __ldg(be2 + t);
#pragma unroll
        for (int b = 0; b < Bc; b++) {
            float z = (a2[b * 64 + t] - m) * sc + sh;
            a2[b * 64 + t] = z > 0.f ? z : 0.f;
        }
    }
    __syncthreads();
    {
        int b = t >> 6, h = t & 63;
        float s = __ldg(b3 + h);
        for (int j = 0; j < 64; j++) s = fmaf(a2[b * 64 + j], __ldg(W3 + j * 64 + h), s);
        a3[t] = s;
    }
    __syncthreads();
    if (t < 64) {
        float m = 0.f;
#pragma unroll
        for (int b = 0; b < Bc; b++) m += a3[b * 64 + t];
        m *= 0.125f;
        float v = 0.f;
#pragma unroll
        for (int b = 0; b < Bc; b++) { float dd = a3[b * 64 + t] - m; v = fmaf(dd, dd, v); }
        v *= 0.125f;
        float sc = rsqrtf(v + EPSc) * __ldg(g3 + t);
        float sh = __ldg(be3 + t);
#pragma unroll
        for (int b = 0; b < Bc; b++) {
            float z = (a3[b * 64 + t] - m) * sc + sh;
            a3[b * 64 + t] = z > 0.f ? z : 0.f;
        }
    }
    __syncthreads();
    if (t < 16) {
        int b = t >> 1, c = t & 1;
        float s = __ldg(b4 + c);
        for (int j = 0; j < 64; j++) s = fmaf(a3[b * 64 + j], __ldg(W4 + j * 2 + c), s);
        lg[t] = s;
    }
    __syncthreads();
    if (t < 8) {
        float l0 = lg[t * 2], l1 = lg[t * 2 + 1];
        float m = fmaxf(l0, l1);
        float lse = m + logf(expf(l0 - m) + expf(l1 - m));
        out[t * 2 + 0] = l0 - lse;
        out[t * 2 + 1] = l1 - lse;
    }
}

// ---------------- host driver ----------------
extern "C" void kernel_launch(void* const* d_in, const int* in_sizes, int n_in,
                              void* d_out, int out_size) {
    const float* x    = (const float*)d_in[0];
    const int*   ei   = (const int*)d_in[1];
    int E = in_sizes[1] / 2;
    const int* src = ei;
    const int* dst = ei + E;
    const float* cw0  = (const float*)d_in[3];
    const float* cb0  = (const float*)d_in[4];
    const float* cw1  = (const float*)d_in[5];
    const float* cb1  = (const float*)d_in[6];
    const float* cw2  = (const float*)d_in[7];
    const float* cb2  = (const float*)d_in[8];
    const float* bnhg = (const float*)d_in[9];
    const float* bnhb = (const float*)d_in[10];
    const float* bng  = (const float*)d_in[11];
    const float* bnb  = (const float*)d_in[12];
    const float* w1   = (const float*)d_in[13];
    const float* b1   = (const float*)d_in[14];
    const float* g1   = (const float*)d_in[15];
    const float* be1  = (const float*)d_in[16];
    const float* W2   = (const float*)d_in[17];
    const float* b2   = (const float*)d_in[18];
    const float* g2   = (const float*)d_in[19];
    const float* be2  = (const float*)d_in[20];
    const float* W3   = (const float*)d_in[21];
    const float* b3   = (const float*)d_in[22];
    const float* g3   = (const float*)d_in[23];
    const float* be3  = (const float*)d_in[24];
    const float* W4   = (const float*)d_in[25];
    const float* b4   = (const float*)d_in[26];
    float* out = (float*)d_out;

    cudaFuncSetAttribute(mega_kernel, cudaFuncAttributeMaxDynamicSharedMemorySize, 65536);
    mega_kernel<<<NB, NTH, 65536>>>(x, src, dst, E,
                                    cw0, cb0, cw1, cb1, cw2, cb2,
                                    bnhg, bnhb, bng, bnb,
                                    w1, b1, g1, be1, W2, b2, g2, be2,
                                    W3, b3, g3, be3, W4, b4, out);
}